// round 1
// baseline (speedup 1.0000x reference)
#include <cuda_runtime.h>
#include <math.h>
#include <float.h>

// ---------------- scratch (device globals; no allocation allowed) ----------
#define MAXC   128
#define MAXC2  256
#define MAXN   65536
#define MAXD   768

__device__ int   g_counts[MAXC];
__device__ int   g_offsets[MAXC + 1];
__device__ int   g_cursor[MAXC];
__device__ int   g_perm[MAXN];
__device__ float g_znorm[MAXC2 * MAXD];
__device__ float g_logits[MAXC2 * MAXC2];   // stride MAXC2
__device__ float g_rowloss[MAXC2];

// ---------------- tiny setup kernels --------------------------------------

__global__ void k_init() {
    int t = threadIdx.x;
    if (t < MAXC) g_counts[t] = 0;
}

__global__ void k_hist(const int* __restrict__ labels, int N, const int* __restrict__ task_id) {
    __shared__ int sh[MAXC];
    int end_i = (*task_id + 1) * 10;
    for (int t = threadIdx.x; t < MAXC; t += blockDim.x) sh[t] = 0;
    __syncthreads();
    int stride = gridDim.x * blockDim.x;
    for (int i = blockIdx.x * blockDim.x + threadIdx.x; i < N; i += stride) {
        int lab = labels[i];
        if (lab >= 0 && lab < end_i) atomicAdd(&sh[lab], 1);
    }
    __syncthreads();
    for (int t = threadIdx.x; t < end_i; t += blockDim.x)
        if (sh[t]) atomicAdd(&g_counts[t], sh[t]);
}

__global__ void k_prefix(const int* __restrict__ task_id) {
    if (threadIdx.x == 0) {
        int end_i = (*task_id + 1) * 10;
        int acc = 0;
        for (int c = 0; c < end_i; c++) {
            g_offsets[c] = acc;
            g_cursor[c]  = acc;
            acc += g_counts[c];
        }
        g_offsets[end_i] = acc;
    }
}

__global__ void k_scatter(const int* __restrict__ labels, int N, const int* __restrict__ task_id) {
    int end_i = (*task_id + 1) * 10;
    int stride = gridDim.x * blockDim.x;
    for (int i = blockIdx.x * blockDim.x + threadIdx.x; i < N; i += stride) {
        int lab = labels[i];
        if (lab >= 0 && lab < end_i) {
            int pos = atomicAdd(&g_cursor[lab], 1);
            g_perm[pos] = i;
        }
    }
}

// ---------------- main segment-sum (HBM-bound) -----------------------------
// grid: (D/256 tiles, 100 classes), 128 threads, float2 per thread, unroll 4.

#define SEG_TPB  128
#define SEG_TILE 256
#define CHUNK    1024

__global__ void __launch_bounds__(SEG_TPB)
k_segsum(const float* __restrict__ z1, const float* __restrict__ z2,
         float* __restrict__ out, int D, const int* __restrict__ task_id) {
    __shared__ int sp[CHUNK];
    int end_i = (*task_id + 1) * 10;
    int c = blockIdx.y;
    if (c >= end_i) return;

    int col  = blockIdx.x * SEG_TILE + threadIdx.x * 2;
    bool act = (col + 1) < D;     // D is even (768)
    int start = g_offsets[c], end = g_offsets[c + 1];

    const float2* __restrict__ z1v = (const float2*)z1;
    const float2* __restrict__ z2v = (const float2*)z2;
    int colv    = col >> 1;
    int strideV = D >> 1;

    float s1x = 0.f, s1y = 0.f, s2x = 0.f, s2y = 0.f;

    for (int base = start; base < end; base += CHUNK) {
        int n = min(CHUNK, end - base);
        __syncthreads();
        for (int t = threadIdx.x; t < n; t += SEG_TPB) sp[t] = g_perm[base + t];
        __syncthreads();
        if (act) {
            int k = 0;
            for (; k + 4 <= n; k += 4) {
                int r0 = sp[k], r1 = sp[k + 1], r2 = sp[k + 2], r3 = sp[k + 3];
                float2 a0 = z1v[(size_t)r0 * strideV + colv];
                float2 a1 = z1v[(size_t)r1 * strideV + colv];
                float2 a2 = z1v[(size_t)r2 * strideV + colv];
                float2 a3 = z1v[(size_t)r3 * strideV + colv];
                float2 b0 = z2v[(size_t)r0 * strideV + colv];
                float2 b1 = z2v[(size_t)r1 * strideV + colv];
                float2 b2 = z2v[(size_t)r2 * strideV + colv];
                float2 b3 = z2v[(size_t)r3 * strideV + colv];
                s1x += (a0.x + a1.x) + (a2.x + a3.x);
                s1y += (a0.y + a1.y) + (a2.y + a3.y);
                s2x += (b0.x + b1.x) + (b2.x + b3.x);
                s2y += (b0.y + b1.y) + (b2.y + b3.y);
            }
            for (; k < n; k++) {
                int r = sp[k];
                float2 a = z1v[(size_t)r * strideV + colv];
                float2 b = z2v[(size_t)r * strideV + colv];
                s1x += a.x; s1y += a.y;
                s2x += b.x; s2y += b.y;
            }
        }
    }

    if (act) {
        int   cnt   = end - start;
        float inv   = 1.0f / (float)max(cnt, 1);
        float* o1 = out + 1 + (size_t)c * D + col;
        o1[0] = s1x * inv;
        o1[1] = s1y * inv;
        float* o2 = out + 1 + (size_t)end_i * D + (size_t)c * D + col;
        o2[0] = s2x * inv;
        o2[1] = s2y * inv;
    }
}

// ---------------- normalize prototypes -> g_znorm --------------------------

__global__ void k_norm(const float* __restrict__ out, int D, const int* __restrict__ task_id) {
    int end_i = (*task_id + 1) * 10;
    int C2    = 2 * end_i;
    int i = blockIdx.x;
    if (i >= C2) return;

    const float* src = out + 1 + (size_t)i * D;  // proto1 rows then proto2 rows, contiguous
    __shared__ float red[256];
    float ssq = 0.f;
    for (int c = threadIdx.x; c < D; c += blockDim.x) {
        float v = src[c];
        ssq += v * v;
    }
    red[threadIdx.x] = ssq;
    __syncthreads();
    for (int s = 128; s > 0; s >>= 1) {
        if (threadIdx.x < s) red[threadIdx.x] += red[threadIdx.x + s];
        __syncthreads();
    }
    float norm  = sqrtf(red[0]);
    float scale = 1.0f / fmaxf(norm, 1e-12f);
    for (int c = threadIdx.x; c < D; c += blockDim.x)
        g_znorm[(size_t)i * MAXD + c] = src[c] * scale;
}

// ---------------- logits = 2 * z z^T (tiled fp32 GEMM) ---------------------

__global__ void __launch_bounds__(256)
k_logits(int D, const int* __restrict__ task_id) {
    int end_i = (*task_id + 1) * 10;
    int C2    = 2 * end_i;
    __shared__ float As[32][33];
    __shared__ float Bs[32][33];
    int tx = threadIdx.x & 31;
    int ty = threadIdx.x >> 5;          // 0..7
    int i0 = blockIdx.y * 32;
    int j0 = blockIdx.x * 32;
    float acc[4] = {0.f, 0.f, 0.f, 0.f};

    for (int kk = 0; kk < D; kk += 32) {
#pragma unroll
        for (int q = 0; q < 4; q++) {
            int r  = ty + 8 * q;
            int ai = i0 + r;
            int bj = j0 + r;
            As[r][tx] = (ai < C2 && kk + tx < D) ? g_znorm[(size_t)ai * MAXD + kk + tx] : 0.f;
            Bs[r][tx] = (bj < C2 && kk + tx < D) ? g_znorm[(size_t)bj * MAXD + kk + tx] : 0.f;
        }
        __syncthreads();
#pragma unroll
        for (int k = 0; k < 32; k++) {
            float b = Bs[tx][k];
#pragma unroll
            for (int q = 0; q < 4; q++) acc[q] += As[ty + 8 * q][k] * b;
        }
        __syncthreads();
    }
#pragma unroll
    for (int q = 0; q < 4; q++) {
        int i = i0 + ty + 8 * q;
        int j = j0 + tx;
        if (i < C2 && j < C2) g_logits[i * MAXC2 + j] = acc[q] * 2.0f;  // 1/T, T=0.5
    }
}

// ---------------- per-row softmax / contrastive term ------------------------
// C2 <= 256, so one thread per column.

__global__ void __launch_bounds__(256)
k_rowloss(const int* __restrict__ task_id) {
    int end_i = (*task_id + 1) * 10;
    int C2    = 2 * end_i;
    int i = blockIdx.x;
    if (i >= C2) return;
    int tid = threadIdx.x;

    __shared__ float red[256];
    __shared__ float sh_m, sh_s;

    bool  vj = false;
    float lv = -FLT_MAX;
    if (tid < C2) {
        int cls = (tid < end_i) ? tid : tid - end_i;
        vj = g_counts[cls] > 0;
        lv = g_logits[i * MAXC2 + tid];
    }

    // row max over valid columns (diagonal included, per reference)
    red[tid] = vj ? lv : -FLT_MAX;
    __syncthreads();
    for (int s = 128; s > 0; s >>= 1) {
        if (tid < s) red[tid] = fmaxf(red[tid], red[tid + s]);
        __syncthreads();
    }
    if (tid == 0) sh_m = red[0];
    __syncthreads();
    float m = sh_m;

    // sum exp over (~eye & valid)
    float e = (tid < C2 && tid != i && vj) ? expf(lv - m) : 0.f;
    red[tid] = e;
    __syncthreads();
    for (int s = 128; s > 0; s >>= 1) {
        if (tid < s) red[tid] += red[tid + s];
        __syncthreads();
    }
    if (tid == 0) sh_s = red[0];
    __syncthreads();
    float S = sh_s;

    int jpos = i + end_i;
    if (jpos >= C2) jpos -= C2;
    if (tid == jpos) {
        int  icls = (i < end_i) ? i : i - end_i;
        bool vi   = g_counts[icls] > 0;
        float lp  = (lv - m) - logf(S);
        g_rowloss[i] = (vi && vj) ? lp : 0.f;
    }
}

// ---------------- deterministic final reduce -------------------------------

__global__ void __launch_bounds__(256)
k_final(float* __restrict__ out, const int* __restrict__ task_id) {
    int end_i = (*task_id + 1) * 10;
    int C2    = 2 * end_i;
    __shared__ float red[256];
    __shared__ int   rin[256];
    int tid = threadIdx.x;

    float l = (tid < C2) ? g_rowloss[tid] : 0.f;
    int   v = 0;
    if (tid < C2) {
        int cls = (tid < end_i) ? tid : tid - end_i;
        v = (g_counts[cls] > 0) ? 1 : 0;
    }
    red[tid] = l;
    rin[tid] = v;
    __syncthreads();
    for (int s = 128; s > 0; s >>= 1) {
        if (tid < s) { red[tid] += red[tid + s]; rin[tid] += rin[tid + s]; }
        __syncthreads();
    }
    if (tid == 0) {
        float nv = (float)rin[0];
        out[0] = -red[0] / fmaxf(nv, 1.0f);
    }
}

// ---------------- launch ----------------------------------------------------

extern "C" void kernel_launch(void* const* d_in, const int* in_sizes, int n_in,
                              void* d_out, int out_size) {
    const float* z1      = (const float*)d_in[0];
    const float* z2      = (const float*)d_in[1];
    const int*   labels  = (const int*)d_in[2];
    const int*   task_id = (const int*)d_in[3];
    float*       out     = (float*)d_out;

    int N = in_sizes[2];
    int D = in_sizes[0] / N;   // 768

    k_init<<<1, 128>>>();
    k_hist<<<64, 256>>>(labels, N, task_id);
    k_prefix<<<1, 32>>>(task_id);
    k_scatter<<<128, 256>>>(labels, N, task_id);

    dim3 gseg((D + SEG_TILE - 1) / SEG_TILE, MAXC > 100 ? 100 : MAXC);
    k_segsum<<<gseg, SEG_TPB>>>(z1, z2, out, D, task_id);

    k_norm<<<200, 256>>>(out, D, task_id);

    dim3 glog((200 + 31) / 32, (200 + 31) / 32);
    k_logits<<<glog, 256>>>(D, task_id);

    k_rowloss<<<200, 256>>>(task_id);
    k_final<<<1, 256>>>(out, task_id);
}

// round 2
// speedup vs baseline: 1.1139x; 1.1139x over previous
#include <cuda_runtime.h>
#include <math.h>
#include <float.h>

// ---------------- scratch (device globals; no allocation allowed) ----------
#define MAXC   128
#define MAXC2  256
#define MAXN   65536
#define MAXD   768
#define RSPLIT 6

__device__ int   g_counts[MAXC];
__device__ int   g_offsets[MAXC + 1];
__device__ int   g_cursor[MAXC];
__device__ int   g_perm[MAXN];
__device__ float g_part[RSPLIT * 100 * 2 * MAXD];   // [r][class][matrix][col]
__device__ float g_znorm[MAXC2 * MAXD];
__device__ float g_logits[MAXC2 * MAXC2];           // stride MAXC2
__device__ float g_rowloss[MAXC2];

// ---------------- tiny setup kernels --------------------------------------

__global__ void k_init() {
    int t = threadIdx.x;
    if (t < MAXC) g_counts[t] = 0;
}

__global__ void k_hist(const int* __restrict__ labels, int N, const int* __restrict__ task_id) {
    __shared__ int sh[MAXC];
    int end_i = (*task_id + 1) * 10;
    for (int t = threadIdx.x; t < MAXC; t += blockDim.x) sh[t] = 0;
    __syncthreads();
    int stride = gridDim.x * blockDim.x;
    for (int i = blockIdx.x * blockDim.x + threadIdx.x; i < N; i += stride) {
        int lab = labels[i];
        if (lab >= 0 && lab < end_i) atomicAdd(&sh[lab], 1);
    }
    __syncthreads();
    for (int t = threadIdx.x; t < end_i; t += blockDim.x)
        if (sh[t]) atomicAdd(&g_counts[t], sh[t]);
}

__global__ void k_prefix(const int* __restrict__ task_id) {
    if (threadIdx.x == 0) {
        int end_i = (*task_id + 1) * 10;
        int acc = 0;
        for (int c = 0; c < end_i; c++) {
            g_offsets[c] = acc;
            g_cursor[c]  = acc;
            acc += g_counts[c];
        }
        g_offsets[end_i] = acc;
    }
}

// Block-aggregated scatter: one global atomic per (block, class) instead of
// one per element.
#define SC_TPB 256
__global__ void __launch_bounds__(SC_TPB)
k_scatter(const int* __restrict__ labels, int N, const int* __restrict__ task_id) {
    __shared__ int lhist[MAXC];
    __shared__ int lbase[MAXC];
    int end_i = (*task_id + 1) * 10;
    int per = (N + gridDim.x - 1) / gridDim.x;
    int b0 = blockIdx.x * per;
    int b1 = min(N, b0 + per);

    for (int t = threadIdx.x; t < MAXC; t += SC_TPB) lhist[t] = 0;
    __syncthreads();
    for (int i = b0 + threadIdx.x; i < b1; i += SC_TPB) {
        int lab = labels[i];
        if (lab >= 0 && lab < end_i) atomicAdd(&lhist[lab], 1);
    }
    __syncthreads();
    for (int c = threadIdx.x; c < end_i; c += SC_TPB) {
        int h = lhist[c];
        lbase[c] = h ? atomicAdd(&g_cursor[c], h) : 0;
    }
    __syncthreads();
    for (int t = threadIdx.x; t < MAXC; t += SC_TPB) lhist[t] = 0;  // reuse as cursor
    __syncthreads();
    for (int i = b0 + threadIdx.x; i < b1; i += SC_TPB) {
        int lab = labels[i];
        if (lab >= 0 && lab < end_i) {
            int pos = lbase[lab] + atomicAdd(&lhist[lab], 1);
            g_perm[pos] = i;
        }
    }
}

// ---------------- main segment-sum (HBM-bound) -----------------------------
// grid (100 classes, RSPLIT row-splits), 192 threads, float4 per thread
// covering the whole 768-col row. Unroll-4 rows -> 8 LDG.128 in flight/thread.

#define SEG_TPB 192
#define CHUNK   128

__global__ void __launch_bounds__(SEG_TPB)
k_segsum(const float* __restrict__ z1, const float* __restrict__ z2,
         const int* __restrict__ task_id) {
    __shared__ int sp[CHUNK];
    int end_i = (*task_id + 1) * 10;
    int c = blockIdx.x;
    int r = blockIdx.y;
    if (c >= end_i) return;

    int start = g_offsets[c], endo = g_offsets[c + 1];
    int len = endo - start;
    int s0 = start + (int)(((long long)len * r) / RSPLIT);
    int s1 = start + (int)(((long long)len * (r + 1)) / RSPLIT);

    const float4* __restrict__ z1v = (const float4*)z1;
    const float4* __restrict__ z2v = (const float4*)z2;
    const int tid = threadIdx.x;
    const int strideV = MAXD / 4;   // 192

    float4 a = make_float4(0.f, 0.f, 0.f, 0.f);
    float4 b = make_float4(0.f, 0.f, 0.f, 0.f);

    for (int base = s0; base < s1; base += CHUNK) {
        int n = min(CHUNK, s1 - base);
        __syncthreads();
        for (int t = tid; t < n; t += SEG_TPB) sp[t] = g_perm[base + t];
        __syncthreads();
        int k = 0;
        for (; k + 4 <= n; k += 4) {
            int r0 = sp[k], r1 = sp[k + 1], r2 = sp[k + 2], r3 = sp[k + 3];
            float4 a0 = z1v[(size_t)r0 * strideV + tid];
            float4 a1 = z1v[(size_t)r1 * strideV + tid];
            float4 a2 = z1v[(size_t)r2 * strideV + tid];
            float4 a3 = z1v[(size_t)r3 * strideV + tid];
            float4 b0 = z2v[(size_t)r0 * strideV + tid];
            float4 b1 = z2v[(size_t)r1 * strideV + tid];
            float4 b2 = z2v[(size_t)r2 * strideV + tid];
            float4 b3 = z2v[(size_t)r3 * strideV + tid];
            a.x += (a0.x + a1.x) + (a2.x + a3.x);
            a.y += (a0.y + a1.y) + (a2.y + a3.y);
            a.z += (a0.z + a1.z) + (a2.z + a3.z);
            a.w += (a0.w + a1.w) + (a2.w + a3.w);
            b.x += (b0.x + b1.x) + (b2.x + b3.x);
            b.y += (b0.y + b1.y) + (b2.y + b3.y);
            b.z += (b0.z + b1.z) + (b2.z + b3.z);
            b.w += (b0.w + b1.w) + (b2.w + b3.w);
        }
        for (; k < n; k++) {
            int rr = sp[k];
            float4 av = z1v[(size_t)rr * strideV + tid];
            float4 bv = z2v[(size_t)rr * strideV + tid];
            a.x += av.x; a.y += av.y; a.z += av.z; a.w += av.w;
            b.x += bv.x; b.y += bv.y; b.z += bv.z; b.w += bv.w;
        }
    }

    float* base = g_part + (((size_t)r * 100 + c) * 2) * MAXD;
    ((float4*)base)[tid]        = a;
    ((float4*)(base + MAXD))[tid] = b;
}

// ---------------- reduce partials + divide + normalize ----------------------

__global__ void __launch_bounds__(256)
k_norm(float* __restrict__ out, const int* __restrict__ task_id) {
    int end_i = (*task_id + 1) * 10;
    int C2    = 2 * end_i;
    int i = blockIdx.x;
    if (i >= C2) return;

    int m = (i >= end_i) ? 1 : 0;
    int c = m ? (i - end_i) : i;
    int cnt = g_counts[c];
    float inv = 1.0f / (float)max(cnt, 1);

    float v[3];
    float ssq = 0.f;
#pragma unroll
    for (int q = 0; q < 3; q++) {
        int col = threadIdx.x + 256 * q;
        float s = 0.f;
#pragma unroll
        for (int r = 0; r < RSPLIT; r++)
            s += g_part[(((size_t)r * 100 + c) * 2 + m) * MAXD + col];
        s *= inv;
        v[q] = s;
        ssq += s * s;
        out[1 + (size_t)i * MAXD + col] = s;
    }

    __shared__ float red[256];
    red[threadIdx.x] = ssq;
    __syncthreads();
    for (int s = 128; s > 0; s >>= 1) {
        if (threadIdx.x < s) red[threadIdx.x] += red[threadIdx.x + s];
        __syncthreads();
    }
    float scale = 1.0f / fmaxf(sqrtf(red[0]), 1e-12f);
#pragma unroll
    for (int q = 0; q < 3; q++) {
        int col = threadIdx.x + 256 * q;
        g_znorm[(size_t)i * MAXD + col] = v[q] * scale;
    }
}

// ---------------- logits = 2 * z z^T (tiled fp32 GEMM) ---------------------

__global__ void __launch_bounds__(256)
k_logits(const int* __restrict__ task_id) {
    int end_i = (*task_id + 1) * 10;
    int C2    = 2 * end_i;
    __shared__ float As[32][33];
    __shared__ float Bs[32][33];
    int tx = threadIdx.x & 31;
    int ty = threadIdx.x >> 5;          // 0..7
    int i0 = blockIdx.y * 32;
    int j0 = blockIdx.x * 32;
    float acc[4] = {0.f, 0.f, 0.f, 0.f};

    for (int kk = 0; kk < MAXD; kk += 32) {
#pragma unroll
        for (int q = 0; q < 4; q++) {
            int r  = ty + 8 * q;
            int ai = i0 + r;
            int bj = j0 + r;
            As[r][tx] = (ai < C2) ? g_znorm[(size_t)ai * MAXD + kk + tx] : 0.f;
            Bs[r][tx] = (bj < C2) ? g_znorm[(size_t)bj * MAXD + kk + tx] : 0.f;
        }
        __syncthreads();
#pragma unroll
        for (int k = 0; k < 32; k++) {
            float b = Bs[tx][k];
#pragma unroll
            for (int q = 0; q < 4; q++) acc[q] += As[ty + 8 * q][k] * b;
        }
        __syncthreads();
    }
#pragma unroll
    for (int q = 0; q < 4; q++) {
        int i = i0 + ty + 8 * q;
        int j = j0 + tx;
        if (i < C2 && j < C2) g_logits[i * MAXC2 + j] = acc[q] * 2.0f;  // 1/T, T=0.5
    }
}

// ---------------- per-row softmax / contrastive term ------------------------

__global__ void __launch_bounds__(256)
k_rowloss(const int* __restrict__ task_id) {
    int end_i = (*task_id + 1) * 10;
    int C2    = 2 * end_i;
    int i = blockIdx.x;
    if (i >= C2) return;
    int tid = threadIdx.x;

    __shared__ float red[256];
    __shared__ float sh_m, sh_s;

    bool  vj = false;
    float lv = -FLT_MAX;
    if (tid < C2) {
        int cls = (tid < end_i) ? tid : tid - end_i;
        vj = g_counts[cls] > 0;
        lv = g_logits[i * MAXC2 + tid];
    }

    red[tid] = vj ? lv : -FLT_MAX;
    __syncthreads();
    for (int s = 128; s > 0; s >>= 1) {
        if (tid < s) red[tid] = fmaxf(red[tid], red[tid + s]);
        __syncthreads();
    }
    if (tid == 0) sh_m = red[0];
    __syncthreads();
    float m = sh_m;

    float e = (tid < C2 && tid != i && vj) ? expf(lv - m) : 0.f;
    red[tid] = e;
    __syncthreads();
    for (int s = 128; s > 0; s >>= 1) {
        if (tid < s) red[tid] += red[tid + s];
        __syncthreads();
    }
    if (tid == 0) sh_s = red[0];
    __syncthreads();
    float S = sh_s;

    int jpos = i + end_i;
    if (jpos >= C2) jpos -= C2;
    if (tid == jpos) {
        int  icls = (i < end_i) ? i : i - end_i;
        bool vi   = g_counts[icls] > 0;
        float lp  = (lv - m) - logf(S);
        g_rowloss[i] = (vi && vj) ? lp : 0.f;
    }
}

// ---------------- deterministic final reduce -------------------------------

__global__ void __launch_bounds__(256)
k_final(float* __restrict__ out, const int* __restrict__ task_id) {
    int end_i = (*task_id + 1) * 10;
    int C2    = 2 * end_i;
    __shared__ float red[256];
    __shared__ int   rin[256];
    int tid = threadIdx.x;

    float l = (tid < C2) ? g_rowloss[tid] : 0.f;
    int   v = 0;
    if (tid < C2) {
        int cls = (tid < end_i) ? tid : tid - end_i;
        v = (g_counts[cls] > 0) ? 1 : 0;
    }
    red[tid] = l;
    rin[tid] = v;
    __syncthreads();
    for (int s = 128; s > 0; s >>= 1) {
        if (tid < s) { red[tid] += red[tid + s]; rin[tid] += rin[tid + s]; }
        __syncthreads();
    }
    if (tid == 0) {
        float nv = (float)rin[0];
        out[0] = -red[0] / fmaxf(nv, 1.0f);
    }
}

// ---------------- launch ----------------------------------------------------

extern "C" void kernel_launch(void* const* d_in, const int* in_sizes, int n_in,
                              void* d_out, int out_size) {
    const float* z1      = (const float*)d_in[0];
    const float* z2      = (const float*)d_in[1];
    const int*   labels  = (const int*)d_in[2];
    const int*   task_id = (const int*)d_in[3];
    float*       out     = (float*)d_out;

    int N = in_sizes[2];

    k_init<<<1, 128>>>();
    k_hist<<<64, 256>>>(labels, N, task_id);
    k_prefix<<<1, 32>>>(task_id);
    k_scatter<<<64, SC_TPB>>>(labels, N, task_id);

    dim3 gseg(100, RSPLIT);
    k_segsum<<<gseg, SEG_TPB>>>(z1, z2, task_id);

    k_norm<<<200, 256>>>(out, task_id);

    dim3 glog(7, 7);
    k_logits<<<glog, 256>>>(task_id);

    k_rowloss<<<200, 256>>>(task_id);
    k_final<<<1, 256>>>(out, task_id);
}

// round 5
// speedup vs baseline: 1.2139x; 1.0898x over previous
#include <cuda_runtime.h>
#include <math.h>
#include <float.h>

// ---------------- scratch (device globals; zero-initialized at load) -------
#define MAXC   128
#define MAXC2  256
#define MAXN   65536
#define MAXD   768
#define RSPLIT 8

__device__ int      g_counts[MAXC];
__device__ int      g_offsets[MAXC + 1];
__device__ int      g_cursor[MAXC];
__device__ int      g_perm[MAXN];
__device__ float    g_part[RSPLIT * 100 * 2 * MAXD];   // [r][class][matrix][col]
__device__ float    g_znorm[MAXC2 * MAXD];             // row-major
__device__ float    g_znormT[MAXD * MAXC2];            // [k][j], cols >=C2 stay 0
__device__ float    g_rowloss[MAXC2];
__device__ unsigned g_ctr1;   // hist completion
__device__ unsigned g_ctr2;   // loss completion

// ---------------- hist + prefix (fused via completion counter) -------------

#define H_TPB 256
__global__ void __launch_bounds__(H_TPB)
k_hist(const int* __restrict__ labels, int N, const int* __restrict__ task_id) {
    __shared__ int sh[MAXC];
    __shared__ bool last;
    int end_i = (*task_id + 1) * 10;
    for (int t = threadIdx.x; t < MAXC; t += H_TPB) sh[t] = 0;
    __syncthreads();
    int stride = gridDim.x * H_TPB;
    for (int i = blockIdx.x * H_TPB + threadIdx.x; i < N; i += stride) {
        int lab = labels[i];
        if (lab >= 0 && lab < end_i) atomicAdd(&sh[lab], 1);
    }
    __syncthreads();
    for (int t = threadIdx.x; t < end_i; t += H_TPB)
        if (sh[t]) atomicAdd(&g_counts[t], sh[t]);
    __threadfence();
    if (threadIdx.x == 0)
        last = (atomicAdd(&g_ctr1, 1u) == gridDim.x - 1);
    __syncthreads();
    if (last && threadIdx.x == 0) {
        int acc = 0;
        for (int c = 0; c < end_i; c++) {
            g_offsets[c] = acc;
            g_cursor[c]  = acc;
            acc += g_counts[c];
        }
        g_offsets[end_i] = acc;
        g_ctr1 = 0;
    }
}

// ---------------- block-aggregated scatter ---------------------------------

#define SC_TPB 256
__global__ void __launch_bounds__(SC_TPB)
k_scatter(const int* __restrict__ labels, int N, const int* __restrict__ task_id) {
    __shared__ int lhist[MAXC];
    __shared__ int lbase[MAXC];
    int end_i = (*task_id + 1) * 10;
    int per = (N + gridDim.x - 1) / gridDim.x;
    int b0 = blockIdx.x * per;
    int b1 = min(N, b0 + per);

    for (int t = threadIdx.x; t < MAXC; t += SC_TPB) lhist[t] = 0;
    __syncthreads();
    for (int i = b0 + threadIdx.x; i < b1; i += SC_TPB) {
        int lab = labels[i];
        if (lab >= 0 && lab < end_i) atomicAdd(&lhist[lab], 1);
    }
    __syncthreads();
    for (int c = threadIdx.x; c < end_i; c += SC_TPB) {
        int h = lhist[c];
        lbase[c] = h ? atomicAdd(&g_cursor[c], h) : 0;
    }
    __syncthreads();
    for (int t = threadIdx.x; t < MAXC; t += SC_TPB) lhist[t] = 0;  // reuse as cursor
    __syncthreads();
    for (int i = b0 + threadIdx.x; i < b1; i += SC_TPB) {
        int lab = labels[i];
        if (lab >= 0 && lab < end_i) {
            int pos = lbase[lab] + atomicAdd(&lhist[lab], 1);
            g_perm[pos] = i;
        }
    }
}

// ---------------- segment-sum (HBM-bound) ----------------------------------
// grid (100 classes, RSPLIT row-splits, 2 matrices), 192 thr, float4/thread.
// One matrix per block -> low regs, 8 LDG.128 in flight, ~64 warps/SM.

#define SEG_TPB 192
#define CHUNK   64

__global__ void __launch_bounds__(SEG_TPB)
k_segsum(const float* __restrict__ z1, const float* __restrict__ z2,
         const int* __restrict__ task_id) {
    __shared__ int sp[CHUNK];
    int end_i = (*task_id + 1) * 10;
    int c = blockIdx.x;
    int r = blockIdx.y;
    int m = blockIdx.z;
    if (c >= end_i) return;

    int start = g_offsets[c], endo = g_offsets[c + 1];
    int len = endo - start;
    int s0 = start + (int)(((long long)len * r) / RSPLIT);
    int s1 = start + (int)(((long long)len * (r + 1)) / RSPLIT);

    const float4* __restrict__ zv = (const float4*)(m ? z2 : z1);
    const int tid = threadIdx.x;
    const int strideV = MAXD / 4;   // 192

    float4 a = make_float4(0.f, 0.f, 0.f, 0.f);

    for (int base = s0; base < s1; base += CHUNK) {
        int n = min(CHUNK, s1 - base);
        __syncthreads();
        for (int t = tid; t < n; t += SEG_TPB) sp[t] = g_perm[base + t];
        __syncthreads();
        int k = 0;
        for (; k + 8 <= n; k += 8) {
            float4 v0 = __ldcs(&zv[(size_t)sp[k]     * strideV + tid]);
            float4 v1 = __ldcs(&zv[(size_t)sp[k + 1] * strideV + tid]);
            float4 v2 = __ldcs(&zv[(size_t)sp[k + 2] * strideV + tid]);
            float4 v3 = __ldcs(&zv[(size_t)sp[k + 3] * strideV + tid]);
            float4 v4 = __ldcs(&zv[(size_t)sp[k + 4] * strideV + tid]);
            float4 v5 = __ldcs(&zv[(size_t)sp[k + 5] * strideV + tid]);
            float4 v6 = __ldcs(&zv[(size_t)sp[k + 6] * strideV + tid]);
            float4 v7 = __ldcs(&zv[(size_t)sp[k + 7] * strideV + tid]);
            a.x += ((v0.x + v1.x) + (v2.x + v3.x)) + ((v4.x + v5.x) + (v6.x + v7.x));
            a.y += ((v0.y + v1.y) + (v2.y + v3.y)) + ((v4.y + v5.y) + (v6.y + v7.y));
            a.z += ((v0.z + v1.z) + (v2.z + v3.z)) + ((v4.z + v5.z) + (v6.z + v7.z));
            a.w += ((v0.w + v1.w) + (v2.w + v3.w)) + ((v4.w + v5.w) + (v6.w + v7.w));
        }
        for (; k < n; k++) {
            float4 v = __ldcs(&zv[(size_t)sp[k] * strideV + tid]);
            a.x += v.x; a.y += v.y; a.z += v.z; a.w += v.w;
        }
    }

    float* base = g_part + (((size_t)r * 100 + c) * 2 + m) * MAXD;
    ((float4*)base)[tid] = a;
}

// ---------------- reduce partials + divide + normalize + transpose ---------

__global__ void __launch_bounds__(256)
k_norm(float* __restrict__ out, const int* __restrict__ task_id) {
    int end_i = (*task_id + 1) * 10;
    int C2    = 2 * end_i;
    int i = blockIdx.x;
    if (i >= C2) return;

    int m = (i >= end_i) ? 1 : 0;
    int c = m ? (i - end_i) : i;
    int cnt = g_counts[c];
    float inv = 1.0f / (float)max(cnt, 1);

    float v[3];
    float ssq = 0.f;
#pragma unroll
    for (int q = 0; q < 3; q++) {
        int col = threadIdx.x + 256 * q;
        float s = 0.f;
#pragma unroll
        for (int r = 0; r < RSPLIT; r++)
            s += g_part[(((size_t)r * 100 + c) * 2 + m) * MAXD + col];
        s *= inv;
        v[q] = s;
        ssq += s * s;
        out[1 + (size_t)i * MAXD + col] = s;
    }

    __shared__ float red[256];
    red[threadIdx.x] = ssq;
    __syncthreads();
    for (int s = 128; s > 0; s >>= 1) {
        if (threadIdx.x < s) red[threadIdx.x] += red[threadIdx.x + s];
        __syncthreads();
    }
    float scale = 1.0f / fmaxf(sqrtf(red[0]), 1e-12f);
#pragma unroll
    for (int q = 0; q < 3; q++) {
        int col = threadIdx.x + 256 * q;
        float zn = v[q] * scale;
        g_znorm[(size_t)i * MAXD + col]  = zn;
        g_znormT[(size_t)col * MAXC2 + i] = zn;
    }
}

// ---------------- fused logits + softmax rowloss + final -------------------
// grid 100 blocks x 256 threads; block b handles rows 2b, 2b+1.
// Thread tid computes logits[i][tid] = 2 * dot(z_i, z_tid) from znormT (L2-hot).

__global__ void __launch_bounds__(256)
k_loss(float* __restrict__ out, const int* __restrict__ task_id) {
    int end_i = (*task_id + 1) * 10;
    int C2    = 2 * end_i;
    int i0 = blockIdx.x * 2;
    int tid = threadIdx.x;

    __shared__ float s0[MAXD], s1[MAXD];
    __shared__ float red[256];
    __shared__ float sh_m, sh_s;
    __shared__ int   shcnt[MAXC];
    __shared__ bool  lastblk;

    bool act = (i0 < C2);

    for (int t = tid; t < MAXC; t += 256) shcnt[t] = g_counts[t];
    if (act) {
        for (int t = tid; t < MAXD; t += 256) {
            s0[t] = g_znorm[(size_t)i0 * MAXD + t];
            s1[t] = g_znorm[(size_t)(i0 + 1) * MAXD + t];
        }
    }
    __syncthreads();

    float l0 = 0.f, l1 = 0.f;
    if (act) {
        float p0[4] = {0.f, 0.f, 0.f, 0.f};
        float p1[4] = {0.f, 0.f, 0.f, 0.f};
        const float* __restrict__ zT = g_znormT;
#pragma unroll 1
        for (int k0 = 0; k0 < MAXD; k0 += 16) {
#pragma unroll
            for (int u = 0; u < 16; u++) {
                float v = zT[(size_t)(k0 + u) * MAXC2 + tid];
                p0[u & 3] = fmaf(s0[k0 + u], v, p0[u & 3]);
                p1[u & 3] = fmaf(s1[k0 + u], v, p1[u & 3]);
            }
        }
        l0 = ((p0[0] + p0[1]) + (p0[2] + p0[3])) * 2.0f;
        l1 = ((p1[0] + p1[1]) + (p1[2] + p1[3])) * 2.0f;
    }

    int  cls = (tid < end_i) ? tid : tid - end_i;
    bool vj  = (tid < C2) && (shcnt[cls] > 0);

    for (int rr = 0; rr < 2; rr++) {
        int   i  = i0 + rr;
        float lv = rr ? l1 : l0;
        if (act) {
            // row max over valid columns
            red[tid] = vj ? lv : -FLT_MAX;
            __syncthreads();
            for (int s = 128; s > 0; s >>= 1) {
                if (tid < s) red[tid] = fmaxf(red[tid], red[tid + s]);
                __syncthreads();
            }
            if (tid == 0) sh_m = red[0];
            __syncthreads();
            float m = sh_m;

            // sum of exp over (~eye & valid)
            red[tid] = (vj && tid != i) ? expf(lv - m) : 0.f;
            __syncthreads();
            for (int s = 128; s > 0; s >>= 1) {
                if (tid < s) red[tid] += red[tid + s];
                __syncthreads();
            }
            if (tid == 0) sh_s = red[0];
            __syncthreads();
            float S = sh_s;

            int jpos = i + end_i;
            if (jpos >= C2) jpos -= C2;
            if (tid == jpos) {
                int  icls = (i < end_i) ? i : i - end_i;
                bool vi   = shcnt[icls] > 0;
                g_rowloss[i] = (vi && vj) ? ((lv - m) - logf(S)) : 0.f;
            }
            __syncthreads();
        }
    }

    // completion counter: last block computes the final loss + resets state
    __threadfence();
    if (tid == 0)
        lastblk = (atomicAdd(&g_ctr2, 1u) == gridDim.x - 1);
    __syncthreads();
    if (lastblk) {
        float l = (tid < C2) ? g_rowloss[tid] : 0.f;
        int   v = vj ? 1 : 0;
        red[tid] = l;
        __syncthreads();
        for (int s = 128; s > 0; s >>= 1) {
            if (tid < s) red[tid] += red[tid + s];
            __syncthreads();
        }
        float lsum = red[0];
        __syncthreads();
        red[tid] = (float)v;
        __syncthreads();
        for (int s = 128; s > 0; s >>= 1) {
            if (tid < s) red[tid] += red[tid + s];
            __syncthreads();
        }
        if (tid == 0) out[0] = -lsum / fmaxf(red[0], 1.0f);
        // reset for next call (zero-state invariant)
        if (tid < MAXC) g_counts[tid] = 0;
        if (tid == 0)   g_ctr2 = 0;
    }
}

// ---------------- launch ----------------------------------------------------

extern "C" void kernel_launch(void* const* d_in, const int* in_sizes, int n_in,
                              void* d_out, int out_size) {
    const float* z1      = (const float*)d_in[0];
    const float* z2      = (const float*)d_in[1];
    const int*   labels  = (const int*)d_in[2];
    const int*   task_id = (const int*)d_in[3];
    float*       out     = (float*)d_out;

    int N = in_sizes[2];

    k_hist<<<64, H_TPB>>>(labels, N, task_id);
    k_scatter<<<64, SC_TPB>>>(labels, N, task_id);

    dim3 gseg(100, RSPLIT, 2);
    k_segsum<<<gseg, SEG_TPB>>>(z1, z2, task_id);

    k_norm<<<200, 256>>>(out, task_id);
    k_loss<<<100, 256>>>(out, task_id);
}